// round 14
// baseline (speedup 1.0000x reference)
#include <cuda_runtime.h>
#include <cuda_fp16.h>
#include <math.h>
#include <stdint.h>

#define NWG   256
#define NP    128
#define NITER 3

#define HALF_G    0.07853981633974483f   // 0.5 * 0.05 * pi
#define HALF_PHIB 1.5707963267948966f    // 0.5 * pi
#define SQ09      0.9486832980505138f    // sqrt(1 - 0.1)

// GEMM tiling (persistent, BM=128)
#define BM 128
#define BN 128
#define BK 64
#define NKCH 8                           // 512 / 64
#define SUBB 8192                        // 8KB sub-block (128 rows x 32 k)
#define A_STG 16384
#define B_STG 16384
#define STG_BYTES (A_STG + B_STG)        // 32KB per stage
#define NSTG 3
#define SMEM_DYN (NSTG * STG_BYTES)      // 96KB
#define NCTA 256                         // grid = (64, 4); all resident at 2/SM

// Tiled global layouts: [tile128][kch32 16][4096 halfs = 8KB pre-swizzled block]
#define A_ELEMS (64 * 16 * 4096)
#define B_ELEMS (4 * 16 * 4096)

// ---------------- device scratch (no allocs allowed) ----------------
__device__ float4 g_coef[NITER * NWG * NP * 2];
__device__ float  g_Rre[NITER * NWG * NWG];
__device__ float  g_Rim[NITER * NWG * NWG];
__device__ __half gBt[NITER * B_ELEMS];
__device__ __half gAt[2][A_ELEMS];
__device__ float gV[8192 * 256];
__device__ int   gSync;

// ---------------- PTX helpers ----------------
__device__ __forceinline__ uint32_t smem_u32(const void* p) {
    return (uint32_t)__cvta_generic_to_shared(p);
}

#define LDSM4(r, addr)                                                         \
    asm volatile("ldmatrix.sync.aligned.m8n8.x4.shared.b16 {%0,%1,%2,%3}, [%4];" \
        : "=r"((r)[0]), "=r"((r)[1]), "=r"((r)[2]), "=r"((r)[3]) : "r"(addr))

__device__ __forceinline__ void mma_f16(float* d, const uint32_t* a,
                                        uint32_t b0, uint32_t b1) {
    asm volatile(
        "mma.sync.aligned.m16n8k16.row.col.f32.f16.f16.f32 "
        "{%0,%1,%2,%3}, {%4,%5,%6,%7}, {%8,%9}, {%0,%1,%2,%3};"
        : "+f"(d[0]), "+f"(d[1]), "+f"(d[2]), "+f"(d[3])
        : "r"(a[0]), "r"(a[1]), "r"(a[2]), "r"(a[3]), "r"(b0), "r"(b1));
}

__device__ __forceinline__ void bulk_g2s(uint32_t dst, const void* src,
                                         uint32_t bytes, uint32_t mb) {
    asm volatile(
        "cp.async.bulk.shared::cluster.global.mbarrier::complete_tx::bytes "
        "[%0], [%1], %2, [%3];"
        :: "r"(dst), "l"(src), "r"(bytes), "r"(mb) : "memory");
}
#define MBAR_INIT(mb, n) asm volatile("mbarrier.init.shared.b64 [%0], %1;" :: "r"(mb), "r"((uint32_t)(n)) : "memory")
#define MBAR_EXPECT_TX(mb, tx) asm volatile("mbarrier.arrive.expect_tx.shared.b64 _, [%0], %1;" :: "r"(mb), "r"((uint32_t)(tx)) : "memory")
#define FENCE_ASYNC() asm volatile("fence.proxy.async.shared::cta;" ::: "memory")

#define MBAR_WAIT(mb, par) do {                                                    \
    uint32_t _mb = (mb); uint32_t _p = (par); uint32_t _done;                      \
    asm volatile("{\n\t.reg .pred p;\n\t"                                          \
        "mbarrier.try_wait.parity.acquire.cta.shared::cta.b64 p, [%1], %2;\n\t"    \
        "selp.b32 %0, 1, 0, p;\n\t}"                                               \
        : "=r"(_done) : "r"(_mb), "r"(_p) : "memory");                             \
    if (!_done) {                                                                  \
        asm volatile("{\n\t.reg .pred P1;\n\t"                                     \
        "WL_%=:\n\t"                                                               \
        "mbarrier.try_wait.parity.acquire.cta.shared::cta.b64 P1, [%0], %1, 0x989680;\n\t" \
        "@P1 bra.uni WD_%=;\n\t"                                                   \
        "bra.uni WL_%=;\n\t"                                                       \
        "WD_%=:\n\t}" :: "r"(_mb), "r"(_p) : "memory");                            \
    } } while (0)

// swizzled byte offset within an 8KB block (row 0..127, 16B chunk c 0..3)
__device__ __forceinline__ uint32_t swz(int row, int c) {
    return (uint32_t)(row * 64 + ((c ^ ((row >> 1) & 3)) << 4));
}

// ============================================================
// Kernel 1: fold theta/phi into MZI 2x2 matrices; zero sync ctr.
// ============================================================
__global__ void coef_kernel(const float* __restrict__ theta,
                            const float* __restrict__ phi) {
    if (blockIdx.x == 0 && threadIdx.x == 0) gSync = 0;
    int t = blockIdx.x * blockDim.x + threadIdx.x;
    const int total = NITER * NWG * NP;
    if (t >= total) return;
    int pair  = t % NP;
    int layer = (t / NP) % NWG;

    float4 c01, c23;
    if ((layer & 1) && pair == NP - 1) {
        c01 = make_float4(1.f, 0.f, 0.f, 0.f);
        c23 = make_float4(0.f, 0.f, 1.f, 0.f);
    } else {
        float h = 0.5f * theta[t];
        float s, c;  sincosf(h, &s, &c);
        float sp, cp; sincosf(phi[t], &sp, &cp);
        float pre_r = -s, pre_i = c;
        float pe_r = pre_r * cp - pre_i * sp;
        float pe_i = pre_r * sp + pre_i * cp;
        c01 = make_float4(pe_r * s,  pe_i * s,   pre_r * c,  pre_i * c);
        c23 = make_float4(pe_r * c,  pe_i * c,  -pre_r * s, -pre_i * s);
    }
    g_coef[2 * t]     = c01;
    g_coef[2 * t + 1] = c23;
}

// ============================================================
// Kernel 2: FUSED register-resident build_R (blocks 0..383)
//           || prep_A (blocks 384..2431). 256 threads.
// ============================================================
__global__ void buildR_prepA_kernel(const float* __restrict__ gamma,
                                    const float* __restrict__ xr,
                                    const float* __restrict__ xi) {
    if (blockIdx.x >= 384) {
        // ---- prep_A role (BM=128 A layout: 8KB blocks) ----
        int t = (blockIdx.x - 384) * 256 + threadIdx.x;   // < 8192*64
        int cq = t & 63, m = t >> 6;
        float4 vr = *(const float4*)(xr + (size_t)m * 256 + cq * 4);
        float4 vi = *(const float4*)(xi + (size_t)m * 256 + cq * 4);
        float re[4] = { vr.x, vr.y, vr.z, vr.w };
        float im[4] = { vi.x, vi.y, vi.z, vi.w };
        __align__(16) __half hb[8];
        #pragma unroll
        for (int q = 0; q < 4; q++) {
            hb[2 * q]     = __float2half_rn(re[q]);
            hb[2 * q + 1] = __float2half_rn(im[q]);
        }
        int mtile = m >> 7, r = m & 127;
        int chunk = cq >> 2, cw = cq & 3;
        size_t base = (size_t)(mtile * 16 + chunk) * 4096;
        size_t off = (size_t)r * 32 + ((cw ^ ((r >> 1) & 3)) << 3);
        *(uint4*)(gAt[0] + base + off) = *(const uint4*)hb;
        return;
    }

    // ---- build_R role: 2 basis rows per block, register-resident ----
    __shared__ float sb[2][2][4][3];
    const int iter = blockIdx.x >> 7;
    const int xblk = blockIdx.x & 127;
    const int p = threadIdx.x & 127;
    const int r = threadIdx.x >> 7;
    const int gj = xblk * 2 + r;
    const int lane = p & 31, wr = p >> 5;

    float x0r = (2 * p     == gj) ? 1.f : 0.f, x0i = 0.f;
    float x1r = (2 * p + 1 == gj) ? 1.f : 0.f, x1i = 0.f;

    const float4* cb = g_coef + (size_t)iter * NWG * NP * 2;
    const int pm1 = (p > 0) ? (p - 1) : 0;

    float4 e01 = cb[(0 * NP + p) * 2];
    float4 e23 = cb[(0 * NP + p) * 2 + 1];
    float4 o01 = cb[(1 * NP + p) * 2];
    float4 o23 = cb[(1 * NP + pm1) * 2 + 1];

    for (int g = 0; g < 128; g++) {
        float4 ne01 = e01, ne23 = e23, no01 = o01, no23 = o23;
        if (g < 127) {
            int le = 2 * (g + 1), lo = le + 1;
            ne01 = cb[(le * NP + p) * 2];
            ne23 = cb[(le * NP + p) * 2 + 1];
            no01 = cb[(lo * NP + p) * 2];
            no23 = cb[(lo * NP + pm1) * 2 + 1];
        }

        {
            float Ar = e01.x, Ai = e01.y, Br = e01.z, Bi = e01.w;
            float Cr = e23.x, Ci = e23.y, Dr = e23.z, Di = e23.w;
            float ar = x0r, ai = x0i, br = x1r, bi = x1i;
            x0r = Ar*ar - Ai*ai + Br*br - Bi*bi;
            x0i = Ar*ai + Ai*ar + Br*bi + Bi*br;
            x1r = Cr*ar - Ci*ai + Dr*br - Di*bi;
            x1i = Cr*ai + Ci*ar + Dr*bi + Di*br;
        }

        const int buf = g & 1;
        if (lane == 0 && wr > 0)  { sb[buf][r][0][wr-1] = x0r; sb[buf][r][1][wr-1] = x0i; }
        if (lane == 31 && wr < 3) { sb[buf][r][2][wr]   = x1r; sb[buf][r][3][wr]   = x1i; }
        __syncthreads();
        float br  = __shfl_down_sync(0xffffffffu, x0r, 1);
        float bi  = __shfl_down_sync(0xffffffffu, x0i, 1);
        float par = __shfl_up_sync(0xffffffffu, x1r, 1);
        float pai = __shfl_up_sync(0xffffffffu, x1i, 1);
        if (lane == 31) {
            if (wr < 3) { br = sb[buf][r][0][wr]; bi = sb[buf][r][1][wr]; }
            else        { br = 0.f; bi = 0.f; }
        }
        if (lane == 0 && wr > 0) { par = sb[buf][r][2][wr-1]; pai = sb[buf][r][3][wr-1]; }
        {
            float Ar = o01.x, Ai = o01.y, Br = o01.z, Bi = o01.w;
            float ar = x1r, ai = x1i;
            float ny1r = Ar*ar - Ai*ai + Br*br - Bi*bi;
            float ny1i = Ar*ai + Ai*ar + Br*bi + Bi*br;
            float Cr = o23.x, Ci = o23.y, Dr = o23.z, Di = o23.w;
            float nx0r = Cr*par - Ci*pai + Dr*x0r - Di*x0i;
            float nx0i = Cr*pai + Ci*par + Dr*x0i + Di*x0r;
            x1r = ny1r; x1i = ny1i;
            if (p > 0) { x0r = nx0r; x0i = nx0i; }
        }
        e01 = ne01; e23 = ne23; o01 = no01; o23 = no23;
    }

    float s0, c0, s1, c1;
    sincosf(gamma[iter * NWG + 2 * p],     &s0, &c0);
    sincosf(gamma[iter * NWG + 2 * p + 1], &s1, &c1);
    size_t rowoff = ((size_t)iter * NWG + gj) * NWG;
    g_Rre[rowoff + 2 * p]     = x0r * c0 - x0i * s0;
    g_Rim[rowoff + 2 * p]     = x0r * s0 + x0i * c0;
    g_Rre[rowoff + 2 * p + 1] = x1r * c1 - x1i * s1;
    g_Rim[rowoff + 2 * p + 1] = x1r * s1 + x1i * c1;
}

// ============================================================
// Kernel 3: pack W^T, coalesced reads (n lane-fast).
// ============================================================
__global__ void pack_W_kernel() {
    int t = blockIdx.x * blockDim.x + threadIdx.x;
    if (t >= NITER * 512 * 64) return;
    int n  = t & 511;               // lane-fast: coalesced R reads
    int kq = (t >> 9) & 63;
    int it = t >> 15;
    int c = n >> 1, nb = n & 1;

    __align__(16) __half hb[8];
    #pragma unroll
    for (int q = 0; q < 8; q++) {
        int k = kq * 8 + q;
        int a = k >> 1, kb = k & 1;
        size_t ri = ((size_t)it * NWG + a) * NWG + c;
        float val;
        if (kb == nb)      val = g_Rre[ri];
        else if (kb == 1)  val = -g_Rim[ri];
        else               val = g_Rim[ri];
        hb[q] = __float2half_rn(val);
    }
    int ntile = n >> 7, r = n & 127;
    int chunk = kq >> 2, cw = kq & 3;
    size_t base = (size_t)it * B_ELEMS + (size_t)(ntile * 16 + chunk) * 4096;
    size_t off = (size_t)r * 32 + ((cw ^ ((r >> 1) & 3)) << 3);
    *(uint4*)(gBt + base + off) = *(const uint4*)hb;
}

// ============================================================
// Kernel 4: PERSISTENT fp16 GEMM: 3 iterations + grid sync +
// fused nonlinearity + fused normalize. grid (64,4) = 256 CTAs,
// 2 CTAs/SM guaranteed by launch_bounds -> all resident.
// ============================================================
__global__ void __launch_bounds__(256, 2) gemm3_kernel(float* __restrict__ out) {
    extern __shared__ char smraw[];
    __shared__ __align__(8) unsigned long long s_mbar[NSTG];
    const uint32_t smem_u = (uint32_t)__cvta_generic_to_shared(smraw);

    const int tid = threadIdx.x;
    const int lane = tid & 31, wid = tid >> 5;
    const int wm = wid & 1, wn = wid >> 1;
    const int m0 = blockIdx.x * BM;
    const int n0 = blockIdx.y * BN;

    uint32_t mb[NSTG];
    #pragma unroll
    for (int s = 0; s < NSTG; s++) mb[s] = smem_u32(&s_mbar[s]);

    int rowA[4], rowB[2];
    #pragma unroll
    for (int ms = 0; ms < 4; ms++)
        rowA[ms] = wm * 64 + ms * 16 + ((lane >> 3) & 1) * 8 + (lane & 7);
    #pragma unroll
    for (int nb = 0; nb < 2; nb++)
        rowB[nb] = wn * 32 + nb * 16 + ((lane >> 3) & 1) * 8 + (lane & 7);
    const int khalf = lane >> 4;

    const int rowbase = m0 + wm * 64 + (lane >> 2);
    const int colbase = n0 + wn * 32 + (lane & 3) * 2;

    for (int iter = 0; iter < NITER; iter++) {
        const int rd = iter & 1;
        const __half* __restrict__ At = gAt[rd] + (size_t)((m0 >> 7) * 16) * 4096;
        const __half* __restrict__ Bt =
            gBt + (size_t)iter * B_ELEMS + (size_t)((n0 >> 7) * 16) * 4096;

        if (tid == 0) {
            #pragma unroll
            for (int s = 0; s < NSTG; s++) MBAR_INIT(mb[s], 1);
        }
        __syncthreads();

        auto issue = [&](int ch) {
            int s = ch % NSTG;
            uint32_t dst = smem_u + s * STG_BYTES;
            MBAR_EXPECT_TX(mb[s], STG_BYTES);
            bulk_g2s(dst,         At + (size_t)ch * 8192, A_STG, mb[s]);
            bulk_g2s(dst + A_STG, Bt + (size_t)ch * 8192, B_STG, mb[s]);
        };
        if (tid == 0) { issue(0); issue(1); }

        float acc[4][4][4];
        #pragma unroll
        for (int i = 0; i < 4; i++)
            #pragma unroll
            for (int j = 0; j < 4; j++)
                #pragma unroll
                for (int q = 0; q < 4; q++) acc[i][j][q] = 0.f;

        for (int ch = 0; ch < NKCH; ch++) {
            const int b = ch % NSTG;
            MBAR_WAIT(mb[b], (ch / NSTG) & 1);
            __syncthreads();
            if (tid == 0 && ch + 2 < NKCH) { FENCE_ASYNC(); issue(ch + 2); }

            const uint32_t stbase = smem_u + b * STG_BYTES;
            #pragma unroll
            for (int kk = 0; kk < 4; kk++) {
                const int kidx = kk * 2 + khalf;
                const uint32_t asub = stbase + (kidx >> 2) * SUBB;
                const uint32_t bsub = stbase + A_STG + (kidx >> 2) * SUBB;
                const int kloc = kidx & 3;
                uint32_t bh[2][4];
                #pragma unroll
                for (int nb = 0; nb < 2; nb++)
                    LDSM4(bh[nb], bsub + swz(rowB[nb], kloc));
                #pragma unroll
                for (int ms = 0; ms < 4; ms++) {
                    uint32_t ah[4];
                    LDSM4(ah, asub + swz(rowA[ms], kloc));
                    #pragma unroll
                    for (int ns = 0; ns < 4; ns++) {
                        int nb = ns >> 1, od = ns & 1;
                        mma_f16(acc[ms][ns], ah, bh[nb][od], bh[nb][2 + od]);
                    }
                }
            }
        }

        // epilogue
        const int nxt = (iter + 1) & 1;
        #pragma unroll
        for (int ms = 0; ms < 4; ms++) {
            #pragma unroll
            for (int ns = 0; ns < 4; ns++) {
                #pragma unroll
                for (int h = 0; h < 2; h++) {
                    int row = rowbase + ms * 16 + h * 8;
                    int col = colbase + ns * 8;
                    float re = acc[ms][ns][2 * h];
                    float im = acc[ms][ns][2 * h + 1];
                    if (iter != NITER - 1) {
                        float phase = HALF_G * (re * re + im * im) + HALF_PHIB;
                        float sp, cp; __sincosf(phase, &sp, &cp);
                        float sc = SQ09 * cp;
                        float yre = sc * (cp * re + sp * im);
                        float yim = sc * (cp * im - sp * re);
                        int mtile = row >> 7, r = row & 127;
                        int chunk = col >> 5, cw = (col >> 3) & 3;
                        size_t base = (size_t)(mtile * 16 + chunk) * 4096;
                        size_t off = (size_t)r * 32 + ((cw ^ ((r >> 1) & 3)) << 3)
                                   + (col & 7);
                        *(__half2*)(gAt[nxt] + base + off) =
                            __half2(__float2half_rn(yre), __float2half_rn(yim));
                    } else {
                        gV[(size_t)row * 256 + (col >> 1)] = re * re + im * im;
                    }
                }
            }
        }

        // ---- grid-wide sync (all 256 CTAs resident) ----
        __threadfence();
        __syncthreads();
        if (tid == 0) {
            atomicAdd(&gSync, 1);
            while (atomicAdd(&gSync, 0) < NCTA * (iter + 1)) __nanosleep(64);
            __threadfence();
        }
        __syncthreads();
    }

    // ---- fused normalize: by==0 CTAs handle their 128 rows ----
    if (blockIdx.y == 0) {
        for (int rr = 0; rr < 16; rr++) {
            int w = m0 + wid * 16 + rr;
            const float* v = gV + (size_t)w * 256;
            float first = 0.f, sum = 0.f;
            #pragma unroll
            for (int j = 0; j < 8; j++) {
                float x = v[lane + 32 * j];
                if (j == 0) first = x;
                sum += x * x;
            }
            #pragma unroll
            for (int o = 16; o; o >>= 1) sum += __shfl_xor_sync(0xFFFFFFFFu, sum, o);
            float inv = 1.f / fmaxf(sqrtf(sum), 1e-12f);
            if (lane < 10) out[w * 10 + lane] = first * inv;
        }
    }
}

// ============================================================
extern "C" void kernel_launch(void* const* d_in, const int* in_sizes, int n_in,
                              void* d_out, int out_size) {
    const float* xre   = (const float*)d_in[0];
    const float* xim   = (const float*)d_in[1];
    const float* theta = (const float*)d_in[2];
    const float* phi   = (const float*)d_in[3];
    const float* gamma = (const float*)d_in[4];
    float* out = (float*)d_out;

    static int attr_set = 0;
    if (!attr_set) {
        cudaFuncSetAttribute(gemm3_kernel,
                             cudaFuncAttributeMaxDynamicSharedMemorySize, SMEM_DYN);
        attr_set = 1;
    }

    coef_kernel<<<(NITER * NWG * NP + 255) / 256, 256>>>(theta, phi);
    buildR_prepA_kernel<<<384 + 2048, 256>>>(gamma, xre, xim);
    pack_W_kernel<<<(NITER * 512 * 64) / 256, 256>>>();
    gemm3_kernel<<<dim3(8192 / BM, 512 / BN), 256, SMEM_DYN>>>(out);
}

// round 15
// speedup vs baseline: 1.3467x; 1.3467x over previous
#include <cuda_runtime.h>
#include <cuda_fp16.h>
#include <math.h>
#include <stdint.h>

#define NWG   256
#define NP    128
#define NITER 3

#define HALF_G    0.07853981633974483f   // 0.5 * 0.05 * pi
#define HALF_PHIB 1.5707963267948966f    // 0.5 * pi
#define SQ09      0.9486832980505138f    // sqrt(1 - 0.1)

// GEMM tiling (R13 config)
#define BM 64
#define BN 128
#define BK 64
#define NKCH 8                           // 512 / 64
#define A_STG 8192                       // 2 x 4KB A blocks
#define B_STG 16384                      // 2 x 8KB B blocks
#define STG_BYTES (A_STG + B_STG)        // 24KB per stage
#define NSTG 3
#define SMEM_DYN (NSTG * STG_BYTES)      // 72KB

// Tiled global layouts (pre-swizzled):
//   A: [mtile64 128][kch32 16][2048 halfs]   B: [ntile128 4][kch32 16][4096 halfs]
#define A_ELEMS (128 * 16 * 2048)
#define B_ELEMS (4 * 16 * 4096)

// ---------------- device scratch (no allocs allowed) ----------------
__device__ float4 g_coef[NITER * NWG * NP * 2];
__device__ __half gBt[NITER * B_ELEMS];
__device__ __half gAt[2][A_ELEMS];
__device__ float gV[8192 * 256];
__device__ int   gCnt[128];

// ---------------- PTX helpers ----------------
__device__ __forceinline__ uint32_t smem_u32(const void* p) {
    return (uint32_t)__cvta_generic_to_shared(p);
}

#define LDSM4(r, addr)                                                         \
    asm volatile("ldmatrix.sync.aligned.m8n8.x4.shared.b16 {%0,%1,%2,%3}, [%4];" \
        : "=r"((r)[0]), "=r"((r)[1]), "=r"((r)[2]), "=r"((r)[3]) : "r"(addr))

__device__ __forceinline__ void mma_f16(float* d, const uint32_t* a,
                                        uint32_t b0, uint32_t b1) {
    asm volatile(
        "mma.sync.aligned.m16n8k16.row.col.f32.f16.f16.f32 "
        "{%0,%1,%2,%3}, {%4,%5,%6,%7}, {%8,%9}, {%0,%1,%2,%3};"
        : "+f"(d[0]), "+f"(d[1]), "+f"(d[2]), "+f"(d[3])
        : "r"(a[0]), "r"(a[1]), "r"(a[2]), "r"(a[3]), "r"(b0), "r"(b1));
}

__device__ __forceinline__ void bulk_g2s(uint32_t dst, const void* src,
                                         uint32_t bytes, uint32_t mb) {
    asm volatile(
        "cp.async.bulk.shared::cluster.global.mbarrier::complete_tx::bytes "
        "[%0], [%1], %2, [%3];"
        :: "r"(dst), "l"(src), "r"(bytes), "r"(mb) : "memory");
}
#define MBAR_INIT(mb, n) asm volatile("mbarrier.init.shared.b64 [%0], %1;" :: "r"(mb), "r"((uint32_t)(n)) : "memory")
#define MBAR_EXPECT_TX(mb, tx) asm volatile("mbarrier.arrive.expect_tx.shared.b64 _, [%0], %1;" :: "r"(mb), "r"((uint32_t)(tx)) : "memory")
#define FENCE_ASYNC() asm volatile("fence.proxy.async.shared::cta;" ::: "memory")

#define MBAR_WAIT(mb, par) do {                                                    \
    uint32_t _mb = (mb); uint32_t _p = (par); uint32_t _done;                      \
    asm volatile("{\n\t.reg .pred p;\n\t"                                          \
        "mbarrier.try_wait.parity.acquire.cta.shared::cta.b64 p, [%1], %2;\n\t"    \
        "selp.b32 %0, 1, 0, p;\n\t}"                                               \
        : "=r"(_done) : "r"(_mb), "r"(_p) : "memory");                             \
    if (!_done) {                                                                  \
        asm volatile("{\n\t.reg .pred P1;\n\t"                                     \
        "WL_%=:\n\t"                                                               \
        "mbarrier.try_wait.parity.acquire.cta.shared::cta.b64 P1, [%0], %1, 0x989680;\n\t" \
        "@P1 bra.uni WD_%=;\n\t"                                                   \
        "bra.uni WL_%=;\n\t"                                                       \
        "WD_%=:\n\t}" :: "r"(_mb), "r"(_p) : "memory");                            \
    } } while (0)

// swizzled byte offset within a pre-swizzled block (64B row stride)
__device__ __forceinline__ uint32_t swz(int row, int c) {
    return (uint32_t)(row * 64 + ((c ^ ((row >> 1) & 3)) << 4));
}

// ============================================================
// Kernel 1: fold theta/phi into MZI 2x2 matrices; zero counters.
// ============================================================
__global__ void coef_kernel(const float* __restrict__ theta,
                            const float* __restrict__ phi) {
    if (blockIdx.x == 0 && threadIdx.x < 128) gCnt[threadIdx.x] = 0;
    int t = blockIdx.x * blockDim.x + threadIdx.x;
    const int total = NITER * NWG * NP;
    if (t >= total) return;
    int pair  = t % NP;
    int layer = (t / NP) % NWG;

    float4 c01, c23;
    if ((layer & 1) && pair == NP - 1) {
        c01 = make_float4(1.f, 0.f, 0.f, 0.f);
        c23 = make_float4(0.f, 0.f, 1.f, 0.f);
    } else {
        float h = 0.5f * theta[t];
        float s, c;  sincosf(h, &s, &c);
        float sp, cp; sincosf(phi[t], &sp, &cp);
        float pre_r = -s, pre_i = c;
        float pe_r = pre_r * cp - pre_i * sp;
        float pe_i = pre_r * sp + pre_i * cp;
        c01 = make_float4(pe_r * s,  pe_i * s,   pre_r * c,  pre_i * c);
        c23 = make_float4(pe_r * c,  pe_i * c,  -pre_r * s, -pre_i * s);
    }
    g_coef[2 * t]     = c01;
    g_coef[2 * t + 1] = c23;
}

// ============================================================
// Kernel 2: FUSED build_R->gBt (blocks 0..95) || prep_A (96..2143).
// build_R: 4 basis rows per thread (8 rows/CTA, 32 CTAs/iter).
// Coef regs shared across the 4 rows -> 4x less L2 coef traffic.
// Writes W^T fp16 directly into gBt (pack_W eliminated).
// ============================================================
__global__ void buildR_prepA_kernel(const float* __restrict__ gamma,
                                    const float* __restrict__ xr,
                                    const float* __restrict__ xi) {
    if (blockIdx.x >= 96) {
        // ---- prep_A role (BM=64 A layout) ----
        int t = (blockIdx.x - 96) * 256 + threadIdx.x;   // < 8192*64
        int cq = t & 63, m = t >> 6;
        float4 vr = *(const float4*)(xr + (size_t)m * 256 + cq * 4);
        float4 vi = *(const float4*)(xi + (size_t)m * 256 + cq * 4);
        float re[4] = { vr.x, vr.y, vr.z, vr.w };
        float im[4] = { vi.x, vi.y, vi.z, vi.w };
        __align__(16) __half hb[8];
        #pragma unroll
        for (int q = 0; q < 4; q++) {
            hb[2 * q]     = __float2half_rn(re[q]);
            hb[2 * q + 1] = __float2half_rn(im[q]);
        }
        int mtile = m >> 6, r = m & 63;
        int chunk = cq >> 2, cw = cq & 3;
        size_t base = (size_t)(mtile * 16 + chunk) * 2048;
        size_t off = (size_t)r * 32 + ((cw ^ ((r >> 1) & 3)) << 3);
        *(uint4*)(gAt[0] + base + off) = *(const uint4*)hb;
        return;
    }

    // ---- build_R role ----
    __shared__ float sb[2][2][4][4][3];  // [buf][group][row][val][slot]
    const int iter = blockIdx.x >> 5;          // 0..2
    const int xblk = blockIdx.x & 31;
    const int p = threadIdx.x & 127;
    const int r = threadIdx.x >> 7;            // row-group 0/1
    const int lane = p & 31, wr = p >> 5;
    const int gjb = xblk * 8 + r * 4;          // rows gjb..gjb+3

    float x0r[4], x0i[4], x1r[4], x1i[4];
    #pragma unroll
    for (int i = 0; i < 4; i++) {
        int gj = gjb + i;
        x0r[i] = (2 * p     == gj) ? 1.f : 0.f;  x0i[i] = 0.f;
        x1r[i] = (2 * p + 1 == gj) ? 1.f : 0.f;  x1i[i] = 0.f;
    }

    const float4* cb = g_coef + (size_t)iter * NWG * NP * 2;
    const int pm1 = (p > 0) ? (p - 1) : 0;

    float4 e01 = cb[(0 * NP + p) * 2];
    float4 e23 = cb[(0 * NP + p) * 2 + 1];
    float4 o01 = cb[(1 * NP + p) * 2];
    float4 o23 = cb[(1 * NP + pm1) * 2 + 1];

    for (int g = 0; g < 128; g++) {
        float4 ne01 = e01, ne23 = e23, no01 = o01, no23 = o23;
        if (g < 127) {
            int le = 2 * (g + 1), lo = le + 1;
            ne01 = cb[(le * NP + p) * 2];
            ne23 = cb[(le * NP + p) * 2 + 1];
            no01 = cb[(lo * NP + p) * 2];
            no23 = cb[(lo * NP + pm1) * 2 + 1];
        }

        // even layer: thread-local per row
        {
            float Ar = e01.x, Ai = e01.y, Br = e01.z, Bi = e01.w;
            float Cr = e23.x, Ci = e23.y, Dr = e23.z, Di = e23.w;
            #pragma unroll
            for (int i = 0; i < 4; i++) {
                float ar = x0r[i], ai = x0i[i], br = x1r[i], bi = x1i[i];
                x0r[i] = Ar*ar - Ai*ai + Br*br - Bi*bi;
                x0i[i] = Ar*ai + Ai*ar + Br*bi + Bi*br;
                x1r[i] = Cr*ar - Ci*ai + Dr*br - Di*bi;
                x1i[i] = Cr*ai + Ci*ar + Dr*bi + Di*br;
            }
        }

        // odd layer boundary exchange
        const int buf = g & 1;
        if (lane == 0 && wr > 0) {
            #pragma unroll
            for (int i = 0; i < 4; i++) {
                sb[buf][r][i][0][wr-1] = x0r[i];
                sb[buf][r][i][1][wr-1] = x0i[i];
            }
        }
        if (lane == 31 && wr < 3) {
            #pragma unroll
            for (int i = 0; i < 4; i++) {
                sb[buf][r][i][2][wr] = x1r[i];
                sb[buf][r][i][3][wr] = x1i[i];
            }
        }
        __syncthreads();

        {
            float Ar = o01.x, Ai = o01.y, Br = o01.z, Bi = o01.w;
            float Cr = o23.x, Ci = o23.y, Dr = o23.z, Di = o23.w;
            #pragma unroll
            for (int i = 0; i < 4; i++) {
                float br  = __shfl_down_sync(0xffffffffu, x0r[i], 1);
                float bi  = __shfl_down_sync(0xffffffffu, x0i[i], 1);
                float par = __shfl_up_sync(0xffffffffu, x1r[i], 1);
                float pai = __shfl_up_sync(0xffffffffu, x1i[i], 1);
                if (lane == 31) {
                    if (wr < 3) { br = sb[buf][r][i][0][wr]; bi = sb[buf][r][i][1][wr]; }
                    else        { br = 0.f; bi = 0.f; }    // pair 127: identity coef
                }
                if (lane == 0 && wr > 0) { par = sb[buf][r][i][2][wr-1]; pai = sb[buf][r][i][3][wr-1]; }
                float ar = x1r[i], ai = x1i[i];
                float ny1r = Ar*ar - Ai*ai + Br*br - Bi*bi;
                float ny1i = Ar*ai + Ai*ar + Br*bi + Bi*br;
                float nx0r = Cr*par - Ci*pai + Dr*x0r[i] - Di*x0i[i];
                float nx0i = Cr*pai + Ci*par + Dr*x0i[i] + Di*x0r[i];
                x1r[i] = ny1r; x1i[i] = ny1i;
                if (p > 0) { x0r[i] = nx0r; x0i[i] = nx0i; }
            }
        }
        e01 = ne01; e23 = ne23; o01 = no01; o23 = no23;
    }

    // gamma rotation + direct fp16 W^T write (replaces g_R + pack_W)
    float s0, c0, s1, c1;
    sincosf(gamma[iter * NWG + 2 * p],     &s0, &c0);
    sincosf(gamma[iter * NWG + 2 * p + 1], &s1, &c1);
    const int ntile = p >> 5;
    const int n0 = 4 * p;
    #pragma unroll
    for (int i = 0; i < 4; i++) {
        int gj = gjb + i;
        float Rr0 = x0r[i] * c0 - x0i[i] * s0;
        float Ri0 = x0r[i] * s0 + x0i[i] * c0;
        float Rr1 = x1r[i] * c1 - x1i[i] * s1;
        float Ri1 = x1r[i] * s1 + x1i[i] * c1;
        __half hr0 = __float2half_rn(Rr0), hi0 = __float2half_rn(Ri0);
        __half hr1 = __float2half_rn(Rr1), hi1 = __float2half_rn(Ri1);
        __half hn0 = __float2half_rn(-Ri0), hn1 = __float2half_rn(-Ri1);

        int k0 = 2 * gj;
        int chunk = k0 >> 5, cw = (k0 >> 3) & 3, ke = k0 & 7;
        size_t base = (size_t)iter * B_ELEMS + (size_t)(ntile * 16 + chunk) * 4096;
        __half2 vals[4] = { __half2(hr0, hn0), __half2(hi0, hr0),
                            __half2(hr1, hn1), __half2(hi1, hr1) };
        #pragma unroll
        for (int j = 0; j < 4; j++) {
            int rr = (n0 + j) & 127;
            size_t off = (size_t)rr * 32 + ((cw ^ ((rr >> 1) & 3)) << 3) + ke;
            *(__half2*)(gBt + base + off) = vals[j];
        }
    }
}

// ============================================================
// Kernel 3: fp16 GEMM (R13 verbatim): BM=64, 3 CTAs/SM,
// 3-stage bulk pipeline, fused normalize on iter==2.
// ============================================================
__global__ void __launch_bounds__(256, 3) gemm_kernel(int iter, float* __restrict__ out) {
    extern __shared__ char smraw[];
    __shared__ __align__(8) unsigned long long s_mbar[NSTG];
    __shared__ int s_last;
    const uint32_t smem_u = (uint32_t)__cvta_generic_to_shared(smraw);

    const int tid = threadIdx.x;
    const int lane = tid & 31, wid = tid >> 5;
    const int wm = wid & 1, wn = wid >> 1;
    const int m0 = blockIdx.x * BM;
    const int n0 = blockIdx.y * BN;
    const int rd = iter & 1;

    const __half* __restrict__ At = gAt[rd] + (size_t)((m0 >> 6) * 16) * 2048;
    const __half* __restrict__ Bt =
        gBt + (size_t)iter * B_ELEMS + (size_t)((n0 >> 7) * 16) * 4096;

    uint32_t mb[NSTG];
    #pragma unroll
    for (int s = 0; s < NSTG; s++) mb[s] = smem_u32(&s_mbar[s]);
    if (tid == 0) {
        #pragma unroll
        for (int s = 0; s < NSTG; s++) MBAR_INIT(mb[s], 1);
    }
    __syncthreads();

    auto issue = [&](int ch) {
        int s = ch % NSTG;
        uint32_t dst = smem_u + s * STG_BYTES;
        MBAR_EXPECT_TX(mb[s], STG_BYTES);
        bulk_g2s(dst,         At + (size_t)ch * 4096, A_STG, mb[s]);
        bulk_g2s(dst + A_STG, Bt + (size_t)ch * 8192, B_STG, mb[s]);
    };

    if (tid == 0) { issue(0); issue(1); }

    int rowA[2], rowB[2];
    #pragma unroll
    for (int ms = 0; ms < 2; ms++)
        rowA[ms] = wm * 32 + ms * 16 + ((lane >> 3) & 1) * 8 + (lane & 7);
    #pragma unroll
    for (int nb = 0; nb < 2; nb++)
        rowB[nb] = wn * 32 + nb * 16 + ((lane >> 3) & 1) * 8 + (lane & 7);
    const int khalf = lane >> 4;

    float acc[2][4][4];
    #pragma unroll
    for (int i = 0; i < 2; i++)
        #pragma unroll
        for (int j = 0; j < 4; j++)
            #pragma unroll
            for (int q = 0; q < 4; q++) acc[i][j][q] = 0.f;

    for (int ch = 0; ch < NKCH; ch++) {
        const int b = ch % NSTG;
        MBAR_WAIT(mb[b], (ch / NSTG) & 1);
        __syncthreads();
        if (tid == 0 && ch + 2 < NKCH) { FENCE_ASYNC(); issue(ch + 2); }

        const uint32_t stbase = smem_u + b * STG_BYTES;
        #pragma unroll
        for (int kk = 0; kk < 4; kk++) {
            const int kidx = kk * 2 + khalf;
            const uint32_t asub = stbase + (kidx >> 2) * 4096;
            const uint32_t bsub = stbase + A_STG + (kidx >> 2) * 8192;
            const int kloc = kidx & 3;
            uint32_t bh[2][4];
            #pragma unroll
            for (int nb = 0; nb < 2; nb++)
                LDSM4(bh[nb], bsub + swz(rowB[nb], kloc));
            #pragma unroll
            for (int ms = 0; ms < 2; ms++) {
                uint32_t ah[4];
                LDSM4(ah, asub + swz(rowA[ms], kloc));
                #pragma unroll
                for (int ns = 0; ns < 4; ns++) {
                    int nb = ns >> 1, od = ns & 1;
                    mma_f16(acc[ms][ns], ah, bh[nb][od], bh[nb][2 + od]);
                }
            }
        }
    }

    const int nxt = (iter + 1) & 1;
    const int rowbase = m0 + wm * 32 + (lane >> 2);
    const int colbase = n0 + wn * 32 + (lane & 3) * 2;

    #pragma unroll
    for (int ms = 0; ms < 2; ms++) {
        #pragma unroll
        for (int ns = 0; ns < 4; ns++) {
            #pragma unroll
            for (int h = 0; h < 2; h++) {
                int row = rowbase + ms * 16 + h * 8;
                int col = colbase + ns * 8;
                float re = acc[ms][ns][2 * h];
                float im = acc[ms][ns][2 * h + 1];
                if (iter != NITER - 1) {
                    float phase = HALF_G * (re * re + im * im) + HALF_PHIB;
                    float sp, cp; __sincosf(phase, &sp, &cp);
                    float sc = SQ09 * cp;
                    float yre = sc * (cp * re + sp * im);
                    float yim = sc * (cp * im - sp * re);
                    int mtile = row >> 6, r = row & 63;
                    int chunk = col >> 5, cw = (col >> 3) & 3;
                    size_t base = (size_t)(mtile * 16 + chunk) * 2048;
                    size_t off = (size_t)r * 32 + ((cw ^ ((r >> 1) & 3)) << 3)
                               + (col & 7);
                    *(__half2*)(gAt[nxt] + base + off) =
                        __half2(__float2half_rn(yre), __float2half_rn(yim));
                } else {
                    gV[(size_t)row * 256 + (col >> 1)] = re * re + im * im;
                }
            }
        }
    }

    if (iter == NITER - 1) {
        __threadfence();
        __syncthreads();
        if (tid == 0) {
            int old = atomicAdd(&gCnt[blockIdx.x], 1);
            s_last = (old == 3);
        }
        __syncthreads();
        if (s_last) {
            __threadfence();
            for (int rr = 0; rr < 8; rr++) {
                int w = m0 + wid * 8 + rr;
                const float* v = gV + (size_t)w * 256;
                float first = 0.f, sum = 0.f;
                #pragma unroll
                for (int j = 0; j < 8; j++) {
                    float x = v[lane + 32 * j];
                    if (j == 0) first = x;
                    sum += x * x;
                }
                #pragma unroll
                for (int o = 16; o; o >>= 1) sum += __shfl_xor_sync(0xFFFFFFFFu, sum, o);
                float inv = 1.f / fmaxf(sqrtf(sum), 1e-12f);
                if (lane < 10) out[w * 10 + lane] = first * inv;
            }
        }
    }
}

// ============================================================
extern "C" void kernel_launch(void* const* d_in, const int* in_sizes, int n_in,
                              void* d_out, int out_size) {
    const float* xre   = (const float*)d_in[0];
    const float* xim   = (const float*)d_in[1];
    const float* theta = (const float*)d_in[2];
    const float* phi   = (const float*)d_in[3];
    const float* gamma = (const float*)d_in[4];
    float* out = (float*)d_out;

    static int attr_set = 0;
    if (!attr_set) {
        cudaFuncSetAttribute(gemm_kernel,
                             cudaFuncAttributeMaxDynamicSharedMemorySize, SMEM_DYN);
        attr_set = 1;
    }

    coef_kernel<<<(NITER * NWG * NP + 255) / 256, 256>>>(theta, phi);
    buildR_prepA_kernel<<<96 + 2048, 256>>>(gamma, xre, xim);
    for (int it = 0; it < NITER; it++)
        gemm_kernel<<<dim3(8192 / BM, 512 / BN), 256, SMEM_DYN>>>(it, out);
}